// round 3
// baseline (speedup 1.0000x reference)
#include <cuda_runtime.h>
#include <cstdint>
#include <cub/cub.cuh>

// ---------------- problem constants ----------------
#define CIN   512
#define NPX   10000           // 100*100
#define NA    9
#define NS    90000           // NPX*NA
#define TOPK  10000
#define NMSW  157             // ceil(TOPK/64)
#define POSTK 2000
#define IMG   1600.0f
#define STRIDE 16.0f
#define XCLIP 4.135166556742356f  // log(1000/16)
#define NMSTHR 0.7f

// ---------------- static device scratch ----------------
__device__ float g_rpn[CIN * NPX];                 // 20 MB
__device__ float g_scores[NS];
__device__ int   g_sidx[NS];
__device__ float g_scores_s[NS];
__device__ int   g_sidx_s[NS];
__device__ float g_deltas[NS * 4];
__device__ float g_bx1[TOPK], g_by1[TOPK], g_bx2[TOPK], g_by2[TOPK];
__device__ float g_bar[TOPK], g_bsc[TOPK];
__device__ unsigned long long g_mask[(size_t)TOPK * NMSW];  // 12.56 MB
__device__ int   g_keep[POSTK];
__device__ __align__(256) unsigned char g_cubtmp[8u << 20];

// ---------------- conv1: 3x3, 512->512, pad 1, ReLU ------------------------
// 64 co x 128 px per block; 256 threads; each thread 8co x 4px.
// fp32 FMA chunks of 72 terms (8 ci x 9 taps), flushed into fp64 accumulators.
__global__ __launch_bounds__(256, 2)
void conv1_kernel(const float* __restrict__ feat,
                  const float* __restrict__ Wc,
                  const float* __restrict__ bc)
{
    __shared__ float w_s[64 * 73];       // [co][ci*9+k], padded row 73
    __shared__ float f_s[8 * 336];       // [ci][330 linear pixels + halo]

    const int tid  = threadIdx.x;
    const int tpx  = tid & 31;           // pixel lane 0..31
    const int tco  = tid >> 5;           // co group 0..7
    const int px0  = blockIdx.x * 128;
    const int cob  = blockIdx.y * 64;
    const int cobase = cob + tco * 8;

    int sb[4];
    int msk[4];
    #pragma unroll
    for (int u = 0; u < 4; u++) {
        int gp = px0 + tpx + 32 * u;
        int y = gp / 100;
        int x = gp - 100 * y;
        int m = 0;
        #pragma unroll
        for (int k = 0; k < 9; k++) {
            int dy = k / 3 - 1, dx = k % 3 - 1;
            int xx = x + dx, yy = y + dy;
            if (xx >= 0 && xx < 100 && yy >= 0 && yy < 100) m |= (1 << k);
        }
        msk[u] = m;
        sb[u]  = tpx + 32 * u + 101;
    }

    double acc[8][4];
    #pragma unroll
    for (int c = 0; c < 8; c++)
        #pragma unroll
        for (int u = 0; u < 4; u++) acc[c][u] = 0.0;

    const int OFFK[9] = {-101, -100, -99, -1, 0, 1, 99, 100, 101};

    for (int ci0 = 0; ci0 < CIN; ci0 += 8) {
        __syncthreads();
        // weights: 64co x 8ci x 9 floats, contiguous over (ci,k)
        for (int t = tid; t < 64 * 72; t += 256) {
            int co = t / 72, r = t - co * 72;
            w_s[co * 73 + r] = Wc[(size_t)(cob + co) * 4608 + (size_t)ci0 * 9 + r];
        }
        // feat halo: 8 ci rows x 330 linear pixels
        for (int t = tid; t < 8 * 330; t += 256) {
            int ci = t / 330, o = t - ci * 330;
            int g = px0 - 101 + o;
            float v = 0.0f;
            if (g >= 0 && g < NPX) v = feat[(size_t)(ci0 + ci) * NPX + g];
            f_s[ci * 336 + o] = v;
        }
        __syncthreads();

        // fp32 chunk of 72 terms
        float ch[8][4];
        #pragma unroll
        for (int c = 0; c < 8; c++)
            #pragma unroll
            for (int u = 0; u < 4; u++) ch[c][u] = 0.0f;

        for (int ci = 0; ci < 8; ci++) {
            const float* fr = &f_s[ci * 336];
            const int wb = tco * 8 * 73 + ci * 9;
            #pragma unroll
            for (int k = 0; k < 9; k++) {
                float fv[4];
                #pragma unroll
                for (int u = 0; u < 4; u++)
                    fv[u] = ((msk[u] >> k) & 1) ? fr[sb[u] + OFFK[k]] : 0.0f;
                #pragma unroll
                for (int c = 0; c < 8; c++) {
                    float w = w_s[wb + c * 73 + k];
                    #pragma unroll
                    for (int u = 0; u < 4; u++)
                        ch[c][u] = fmaf(w, fv[u], ch[c][u]);
                }
            }
        }
        // flush chunk into fp64 master accumulators
        #pragma unroll
        for (int c = 0; c < 8; c++)
            #pragma unroll
            for (int u = 0; u < 4; u++)
                acc[c][u] += (double)ch[c][u];
    }

    #pragma unroll
    for (int u = 0; u < 4; u++) {
        int gp = px0 + tpx + 32 * u;
        if (gp < NPX) {
            #pragma unroll
            for (int c = 0; c < 8; c++) {
                double v = acc[c][u] + (double)bc[cobase + c];
                float r = (float)v;
                g_rpn[(size_t)(cobase + c) * NPX + gp] = fmaxf(r, 0.0f);
            }
        }
    }
}

// ---------------- conv2: 1x1 heads, fp64 accumulation ----------------------
// 160 threads = 5 c-groups x 32 lanes; each thread 9 channels x 4 pixels.
__global__ __launch_bounds__(160)
void conv2_kernel(const float* __restrict__ Wcls, const float* __restrict__ bcls,
                  const float* __restrict__ Wbb,  const float* __restrict__ bbb)
{
    __shared__ float ws[45 * 128];
    const int tid  = threadIdx.x;
    const int cg   = tid >> 5;    // 0..4
    const int lane = tid & 31;
    const int px0  = blockIdx.x * 128;

    int gp[4];
    #pragma unroll
    for (int u = 0; u < 4; u++) gp[u] = px0 + lane + 32 * u;

    double acc[9][4];
    #pragma unroll
    for (int c = 0; c < 9; c++)
        #pragma unroll
        for (int u = 0; u < 4; u++) acc[c][u] = 0.0;

    for (int ci0 = 0; ci0 < CIN; ci0 += 128) {
        __syncthreads();
        for (int t = tid; t < 45 * 128; t += 160) {
            int c = t >> 7, o = t & 127;
            ws[t] = (c < 9) ? Wcls[c * CIN + ci0 + o] : Wbb[(c - 9) * CIN + ci0 + o];
        }
        __syncthreads();
        for (int ci = 0; ci < 128; ci++) {
            const float* rp = &g_rpn[(size_t)(ci0 + ci) * NPX];
            double f[4];
            #pragma unroll
            for (int u = 0; u < 4; u++)
                f[u] = (gp[u] < NPX) ? (double)rp[gp[u]] : 0.0;
            #pragma unroll
            for (int c9 = 0; c9 < 9; c9++) {
                double w = (double)ws[(cg * 9 + c9) * 128 + ci];
                #pragma unroll
                for (int u = 0; u < 4; u++)
                    acc[c9][u] = fma(w, f[u], acc[c9][u]);
            }
        }
    }

    #pragma unroll
    for (int u = 0; u < 4; u++) {
        if (gp[u] >= NPX) continue;
        int p = gp[u];
        if (cg == 0) {
            #pragma unroll
            for (int a = 0; a < 9; a++) {
                float xl = (float)(acc[a][u] + (double)bcls[a]);
                // XLA LogisticExpander: logistic(x) = 0.5 + 0.5*tanh(0.5*x);
                // XLA-GPU tanh f32 -> libdevice __nv_tanhf == CUDA tanhf
                float sc = 0.5f + 0.5f * tanhf(0.5f * xl);
                int si = p * 9 + a;
                g_scores[si] = sc;
                g_sidx[si]   = si;
            }
        } else {
            #pragma unroll
            for (int c9 = 0; c9 < 9; c9++) {
                int cc = (cg - 1) * 9 + c9;       // bbox channel 0..35
                int a = cc >> 2, comp = cc & 3;
                float v = (float)(acc[c9][u] + (double)bbb[cc]);
                g_deltas[(size_t)(p * 9 + a) * 4 + comp] = v;
            }
        }
    }
}

// ---------------- decode top-10000 boxes ----------------
__global__ void decode_kernel()
{
    int i = blockIdx.x * 256 + threadIdx.x;
    if (i >= TOPK) return;
    int idx  = g_sidx_s[i];
    float sc = g_scores_s[i];
    int a = idx % 9;
    int p = idx / 9;
    int x = p % 100, y = p / 100;

    int r = a / 3, s = a % 3;
    float ratio = (r == 0) ? 0.5f : (r == 1) ? 1.0f : 2.0f;
    float scale = (s == 0) ? 128.0f : (s == 1) ? 256.0f : 512.0f;
    float hr = sqrtf(ratio);
    float wr = 1.0f / hr;
    float ws = wr * scale, hs = hr * scale;

    float ax1 = x * STRIDE + rintf(-ws * 0.5f);
    float ay1 = y * STRIDE + rintf(-hs * 0.5f);
    float ax2 = x * STRIDE + rintf( ws * 0.5f);
    float ay2 = y * STRIDE + rintf( hs * 0.5f);

    float w  = ax2 - ax1;
    float h  = ay2 - ay1;
    float cx = ax1 + 0.5f * w;
    float cy = ay1 + 0.5f * h;

    const float4 dl = *reinterpret_cast<const float4*>(&g_deltas[(size_t)idx * 4]);
    float dx = dl.x, dy = dl.y;
    float dw = fminf(dl.z, XCLIP);
    float dh = fminf(dl.w, XCLIP);

    float pcx = dx * w + cx;
    float pcy = dy * h + cy;
    float pw  = expf(dw) * w;
    float ph  = expf(dh) * h;

    float x1 = fminf(fmaxf(pcx - 0.5f * pw, 0.0f), IMG);
    float y1 = fminf(fmaxf(pcy - 0.5f * ph, 0.0f), IMG);
    float x2 = fminf(fmaxf(pcx + 0.5f * pw, 0.0f), IMG);
    float y2 = fminf(fmaxf(pcy + 0.5f * ph, 0.0f), IMG);

    g_bx1[i] = x1; g_by1[i] = y1; g_bx2[i] = x2; g_by2[i] = y2;
    g_bar[i] = (x2 - x1) * (y2 - y1);
    g_bsc[i] = sc;
}

// ---------------- NMS bitmask ----------------
__global__ void nms_mask_kernel()
{
    const int bi = blockIdx.y, bj = blockIdx.x;
    const int t  = threadIdx.x;
    if (bj < bi) return;

    __shared__ float sx1[64], sy1[64], sx2[64], sy2[64], sa[64];
    int j0 = bj * 64;
    int j  = j0 + t;
    if (j < TOPK) {
        sx1[t] = g_bx1[j]; sy1[t] = g_by1[j];
        sx2[t] = g_bx2[j]; sy2[t] = g_by2[j];
        sa[t]  = g_bar[j];
    }
    __syncthreads();

    int i = bi * 64 + t;
    if (i >= TOPK) return;
    float bx1 = g_bx1[i], by1 = g_by1[i], bx2 = g_bx2[i], by2 = g_by2[i], ba = g_bar[i];

    unsigned long long bits = 0;
    int jmax = min(64, TOPK - j0);
    for (int jj = 0; jj < jmax; jj++) {
        int jg = j0 + jj;
        if (jg <= i) continue;
        float ix = fminf(bx2, sx2[jj]) - fmaxf(bx1, sx1[jj]);
        float iy = fminf(by2, sy2[jj]) - fmaxf(by1, sy1[jj]);
        ix = fmaxf(ix, 0.0f);
        iy = fmaxf(iy, 0.0f);
        float inter = ix * iy;
        float iou = inter / (ba + sa[jj] - inter);
        if (iou > NMSTHR) bits |= (1ULL << jj);
    }
    g_mask[(size_t)i * NMSW + bj] = bits;
}

// ---------------- sequential greedy scan + compaction ----------------
__global__ void nms_scan_kernel()
{
    __shared__ unsigned long long s_alive;
    __shared__ int s_cnt;
    const int t = threadIdx.x;
    if (t == 0) s_cnt = 0;
    for (int j = t; j < POSTK; j += blockDim.x) g_keep[j] = 0;

    unsigned long long remv = 0;

    for (int b = 0; b < NMSW; b++) {
        __syncthreads();
        if (t == b) {
            unsigned long long w = remv;
            unsigned long long alive = 0;
            int n = min(64, TOPK - b * 64);
            int cnt = s_cnt;
            for (int bit = 0; bit < n; bit++) {
                if (!((w >> bit) & 1ULL)) {
                    int i = b * 64 + bit;
                    alive |= (1ULL << bit);
                    if (cnt < POSTK) g_keep[cnt++] = i;
                    w |= g_mask[(size_t)i * NMSW + b];
                }
            }
            s_cnt = cnt;
            s_alive = alive;
            remv = w;
        }
        __syncthreads();
        if (t < NMSW && t > b) {
            unsigned long long am = s_alive;
            while (am) {
                int bit = __ffsll((long long)am) - 1;
                am &= (am - 1);
                remv |= g_mask[(size_t)(b * 64 + bit) * NMSW + t];
            }
        }
    }
}

// ---------------- gather output [2000,5] ----------------
__global__ void output_kernel(float* __restrict__ out)
{
    int j = blockIdx.x * 256 + threadIdx.x;
    if (j >= POSTK) return;
    int k = g_keep[j];
    out[j * 5 + 0] = g_bx1[k];
    out[j * 5 + 1] = g_by1[k];
    out[j * 5 + 2] = g_bx2[k];
    out[j * 5 + 3] = g_by2[k];
    out[j * 5 + 4] = g_bsc[k];
}

// ---------------- host launch ----------------
extern "C" void kernel_launch(void* const* d_in, const int* in_sizes, int n_in,
                              void* d_out, int out_size)
{
    (void)in_sizes; (void)n_in; (void)out_size;
    const float* feat  = (const float*)d_in[1];
    const float* Wconv = (const float*)d_in[2];
    const float* bconv = (const float*)d_in[3];
    const float* Wcls  = (const float*)d_in[4];
    const float* bcls  = (const float*)d_in[5];
    const float* Wbb   = (const float*)d_in[6];
    const float* bbb   = (const float*)d_in[7];
    float* out = (float*)d_out;

    void *p_sc, *p_idx, *p_scs, *p_idxs, *p_tmp;
    cudaGetSymbolAddress(&p_sc,   g_scores);
    cudaGetSymbolAddress(&p_idx,  g_sidx);
    cudaGetSymbolAddress(&p_scs,  g_scores_s);
    cudaGetSymbolAddress(&p_idxs, g_sidx_s);
    cudaGetSymbolAddress(&p_tmp,  g_cubtmp);

    conv1_kernel<<<dim3(79, 8), 256>>>(feat, Wconv, bconv);
    conv2_kernel<<<79, 160>>>(Wcls, bcls, Wbb, bbb);

    size_t tmp_bytes = sizeof(g_cubtmp);
    cub::DeviceRadixSort::SortPairsDescending(
        p_tmp, tmp_bytes,
        (const float*)p_sc, (float*)p_scs,
        (const int*)p_idx,  (int*)p_idxs,
        NS, 0, 32, (cudaStream_t)0);

    decode_kernel<<<40, 256>>>();
    nms_mask_kernel<<<dim3(NMSW, NMSW), 64>>>();
    nms_scan_kernel<<<1, 192>>>();
    output_kernel<<<8, 256>>>(out);
}

// round 4
// speedup vs baseline: 2.5470x; 2.5470x over previous
#include <cuda_runtime.h>
#include <cstdint>
#include <cub/cub.cuh>

// ---------------- problem constants ----------------
#define CIN   512
#define NPX   10000           // 100*100
#define NA    9
#define NS    90000           // NPX*NA
#define TOPK  10000
#define NMSW  157             // ceil(TOPK/64)
#define POSTK 2000
#define IMG   1600.0f
#define STRIDE 16.0f
#define XCLIP 4.135166556742356f  // log(1000/16)
#define NMSTHR 0.7f

// ---------------- static device scratch ----------------
__device__ float g_rpn[CIN * NPX];                 // 20 MB
__device__ float g_scores[NS];
__device__ int   g_sidx[NS];
__device__ float g_scores_s[NS];
__device__ int   g_sidx_s[NS];
__device__ float g_deltas[NS * 4];
__device__ float g_bx1[TOPK], g_by1[TOPK], g_bx2[TOPK], g_by2[TOPK];
__device__ float g_bar[TOPK], g_bsc[TOPK];
__device__ unsigned long long g_mask[(size_t)TOPK * NMSW];  // 12.56 MB
__device__ int   g_keep[POSTK];
__device__ __align__(256) unsigned char g_cubtmp[8u << 20];

// ---------------- f32x2 packed helpers (Blackwell) ----------------
__device__ __forceinline__ unsigned long long ffma2(unsigned long long a,
                                                    unsigned long long b,
                                                    unsigned long long c)
{
    unsigned long long d;
    asm("fma.rn.f32x2 %0, %1, %2, %3;" : "=l"(d) : "l"(a), "l"(b), "l"(c));
    return d;
}
__device__ __forceinline__ unsigned long long dup_f32(float x)
{
    unsigned int u = __float_as_uint(x);
    unsigned long long d;
    asm("mov.b64 %0, {%1, %1};" : "=l"(d) : "r"(u));
    return d;
}
__device__ __forceinline__ void unpack_f32x2(unsigned long long v, float& lo, float& hi)
{
    unsigned int a, b;
    asm("mov.b64 {%0, %1}, %2;" : "=r"(a), "=r"(b) : "l"(v));
    lo = __uint_as_float(a);
    hi = __uint_as_float(b);
}

// ---------------- cp.async helpers ----------------
__device__ __forceinline__ unsigned int smem_u32(const void* p)
{
    return (unsigned int)__cvta_generic_to_shared(p);
}
__device__ __forceinline__ void cpa4(unsigned int dst, const void* src, int src_bytes)
{
    asm volatile("cp.async.ca.shared.global [%0], [%1], 4, %2;"
                 :: "r"(dst), "l"(src), "r"(src_bytes));
}
__device__ __forceinline__ void cpa_commit()
{
    asm volatile("cp.async.commit_group;");
}

// ---------------- conv1: 3x3, 512->512, pad 1, ReLU ------------------------
// 64 co x 128 px per block; 256 threads; each thread 8co x 4px.
// Inner math: fma.rn.f32x2 over (co, co+1) pairs; each pair-lane is a
// sequential 72-term fp32 chain (8ci x 9 taps) flushed into fp64 masters —
// same numeric scheme as the validated round-3 kernel.
// Weights staged TRANSPOSED in smem: w_s[r*68 + co] so the a-frag for 8 co
// is one ulonglong2 (LDS.128) = 4 packed pairs. cp.async double-buffered.
#define W_STRIDE 68
#define W_CHUNK  (72 * W_STRIDE)     // floats per weight buffer
#define F_CHUNK  (8 * 336)           // floats per feat buffer
#define CONV1_SMEM ((2 * W_CHUNK + 2 * F_CHUNK) * 4)

__global__ __launch_bounds__(256, 1)
void conv1_kernel(const float* __restrict__ feat,
                  const float* __restrict__ Wc,
                  const float* __restrict__ bc)
{
    extern __shared__ float sm[];
    float* wbuf[2] = { sm, sm + W_CHUNK };
    float* fbuf[2] = { sm + 2 * W_CHUNK, sm + 2 * W_CHUNK + F_CHUNK };

    const int tid  = threadIdx.x;
    const int tpx  = tid & 31;           // pixel lane 0..31
    const int tco  = tid >> 5;           // co group 0..7
    const int px0  = blockIdx.x * 128;
    const int cob  = blockIdx.y * 64;
    const int cobase = cob + tco * 8;

    int sb[4];
    int msk[4];
    #pragma unroll
    for (int u = 0; u < 4; u++) {
        int gp = px0 + tpx + 32 * u;
        int y = gp / 100;
        int x = gp - 100 * y;
        int m = 0;
        #pragma unroll
        for (int k = 0; k < 9; k++) {
            int dy = k / 3 - 1, dx = k % 3 - 1;
            int xx = x + dx, yy = y + dy;
            if (xx >= 0 && xx < 100 && yy >= 0 && yy < 100) m |= (1 << k);
        }
        msk[u] = m;
        sb[u]  = tpx + 32 * u + 101;
    }

    double acc[8][4];
    #pragma unroll
    for (int c = 0; c < 8; c++)
        #pragma unroll
        for (int u = 0; u < 4; u++) acc[c][u] = 0.0;

    const int OFFK[9] = {-101, -100, -99, -1, 0, 1, 99, 100, 101};

    // ---- async stage of one 8-ci chunk into buffer s ----
    auto stage = [&](int s, int ci0) {
        float* wd = wbuf[s];
        float* fd = fbuf[s];
        // weights: 64 co x 72 (ci*9+k) -> transposed smem [r*68 + co]
        const float* wg = Wc + (size_t)cob * 4608 + (size_t)ci0 * 9;
        for (int t = tid; t < 64 * 72; t += 256) {
            int co = t / 72, r = t - co * 72;     // gmem contiguous in r
            cpa4(smem_u32(&wd[r * W_STRIDE + co]), wg + (size_t)co * 4608 + r, 4);
        }
        // feat halo: 8 ci rows x 330 linear pixels, zero-fill out of range
        for (int t = tid; t < 8 * 330; t += 256) {
            int ci = t / 330, o = t - ci * 330;
            int g = px0 - 101 + o;
            int ok = (g >= 0 && g < NPX) ? 4 : 0;
            const float* src = feat + (size_t)(ci0 + ci) * NPX + (ok ? g : 0);
            cpa4(smem_u32(&fd[ci * 336 + o]), src, ok);
        }
        cpa_commit();
    };

    stage(0, 0);

    for (int cch = 0; cch < 64; cch++) {
        const int cur = cch & 1;
        if (cch + 1 < 64) {
            stage(cur ^ 1, (cch + 1) * 8);
            asm volatile("cp.async.wait_group 1;");
        } else {
            asm volatile("cp.async.wait_group 0;");
        }
        __syncthreads();

        const float* wc_ = wbuf[cur];
        const float* fc_ = fbuf[cur];

        // fp32 chunk accumulators: 4 co-pairs x 4 px, packed f32x2
        unsigned long long ch2[4][4];
        #pragma unroll
        for (int c2 = 0; c2 < 4; c2++)
            #pragma unroll
            for (int u = 0; u < 4; u++) ch2[c2][u] = 0ULL;

        for (int ci = 0; ci < 8; ci++) {
            const float* fr = fc_ + ci * 336;
            const int rb = ci * 9;
            #pragma unroll
            for (int k = 0; k < 9; k++) {
                const ulonglong2* wp =
                    (const ulonglong2*)(wc_ + (rb + k) * W_STRIDE + tco * 8);
                ulonglong2 wA = wp[0];      // pairs (co0,co1),(co2,co3)
                ulonglong2 wB = wp[1];      // pairs (co4,co5),(co6,co7)

                unsigned long long d[4];
                #pragma unroll
                for (int u = 0; u < 4; u++) {
                    float fv = ((msk[u] >> k) & 1) ? fr[sb[u] + OFFK[k]] : 0.0f;
                    d[u] = dup_f32(fv);
                }
                #pragma unroll
                for (int u = 0; u < 4; u++) {
                    ch2[0][u] = ffma2(wA.x, d[u], ch2[0][u]);
                    ch2[1][u] = ffma2(wA.y, d[u], ch2[1][u]);
                    ch2[2][u] = ffma2(wB.x, d[u], ch2[2][u]);
                    ch2[3][u] = ffma2(wB.y, d[u], ch2[3][u]);
                }
            }
        }

        // flush 72-term fp32 chunks into fp64 masters
        #pragma unroll
        for (int c2 = 0; c2 < 4; c2++)
            #pragma unroll
            for (int u = 0; u < 4; u++) {
                float lo, hi;
                unpack_f32x2(ch2[c2][u], lo, hi);
                acc[2 * c2 + 0][u] += (double)lo;
                acc[2 * c2 + 1][u] += (double)hi;
            }
        __syncthreads();
    }

    #pragma unroll
    for (int u = 0; u < 4; u++) {
        int gp = px0 + tpx + 32 * u;
        if (gp < NPX) {
            #pragma unroll
            for (int c = 0; c < 8; c++) {
                double v = acc[c][u] + (double)bc[cobase + c];
                float r = (float)v;
                g_rpn[(size_t)(cobase + c) * NPX + gp] = fmaxf(r, 0.0f);
            }
        }
    }
}

// ---------------- conv2: 1x1 heads, fp64 accumulation ----------------------
// 157 blocks x 64 px; 160 threads = 5 c-groups x 32 lanes; 9ch x 2px each.
__global__ __launch_bounds__(160)
void conv2_kernel(const float* __restrict__ Wcls, const float* __restrict__ bcls,
                  const float* __restrict__ Wbb,  const float* __restrict__ bbb)
{
    __shared__ float ws[45 * 128];
    const int tid  = threadIdx.x;
    const int cg   = tid >> 5;    // 0..4
    const int lane = tid & 31;
    const int px0  = blockIdx.x * 64;

    int gp[2];
    #pragma unroll
    for (int u = 0; u < 2; u++) gp[u] = px0 + lane + 32 * u;

    double acc[9][2];
    #pragma unroll
    for (int c = 0; c < 9; c++)
        #pragma unroll
        for (int u = 0; u < 2; u++) acc[c][u] = 0.0;

    for (int ci0 = 0; ci0 < CIN; ci0 += 128) {
        __syncthreads();
        for (int t = tid; t < 45 * 128; t += 160) {
            int c = t >> 7, o = t & 127;
            ws[t] = (c < 9) ? Wcls[c * CIN + ci0 + o] : Wbb[(c - 9) * CIN + ci0 + o];
        }
        __syncthreads();
        for (int ci = 0; ci < 128; ci++) {
            const float* rp = &g_rpn[(size_t)(ci0 + ci) * NPX];
            double f[2];
            #pragma unroll
            for (int u = 0; u < 2; u++)
                f[u] = (gp[u] < NPX) ? (double)rp[gp[u]] : 0.0;
            #pragma unroll
            for (int c9 = 0; c9 < 9; c9++) {
                double w = (double)ws[(cg * 9 + c9) * 128 + ci];
                #pragma unroll
                for (int u = 0; u < 2; u++)
                    acc[c9][u] = fma(w, f[u], acc[c9][u]);
            }
        }
    }

    #pragma unroll
    for (int u = 0; u < 2; u++) {
        if (gp[u] >= NPX) continue;
        int p = gp[u];
        if (cg == 0) {
            #pragma unroll
            for (int a = 0; a < 9; a++) {
                float xl = (float)(acc[a][u] + (double)bcls[a]);
                // XLA LogisticExpander: logistic(x) = 0.5 + 0.5*tanh(0.5*x)
                float sc = 0.5f + 0.5f * tanhf(0.5f * xl);
                int si = p * 9 + a;
                g_scores[si] = sc;
                g_sidx[si]   = si;
            }
        } else {
            #pragma unroll
            for (int c9 = 0; c9 < 9; c9++) {
                int cc = (cg - 1) * 9 + c9;       // bbox channel 0..35
                int a = cc >> 2, comp = cc & 3;
                float v = (float)(acc[c9][u] + (double)bbb[cc]);
                g_deltas[(size_t)(p * 9 + a) * 4 + comp] = v;
            }
        }
    }
}

// ---------------- decode top-10000 boxes ----------------
__global__ void decode_kernel()
{
    int i = blockIdx.x * 256 + threadIdx.x;
    if (i >= TOPK) return;
    int idx  = g_sidx_s[i];
    float sc = g_scores_s[i];
    int a = idx % 9;
    int p = idx / 9;
    int x = p % 100, y = p / 100;

    int r = a / 3, s = a % 3;
    float ratio = (r == 0) ? 0.5f : (r == 1) ? 1.0f : 2.0f;
    float scale = (s == 0) ? 128.0f : (s == 1) ? 256.0f : 512.0f;
    float hr = sqrtf(ratio);
    float wr = 1.0f / hr;
    float ws = wr * scale, hs = hr * scale;

    float ax1 = x * STRIDE + rintf(-ws * 0.5f);
    float ay1 = y * STRIDE + rintf(-hs * 0.5f);
    float ax2 = x * STRIDE + rintf( ws * 0.5f);
    float ay2 = y * STRIDE + rintf( hs * 0.5f);

    float w  = ax2 - ax1;
    float h  = ay2 - ay1;
    float cx = ax1 + 0.5f * w;
    float cy = ay1 + 0.5f * h;

    const float4 dl = *reinterpret_cast<const float4*>(&g_deltas[(size_t)idx * 4]);
    float dx = dl.x, dy = dl.y;
    float dw = fminf(dl.z, XCLIP);
    float dh = fminf(dl.w, XCLIP);

    float pcx = dx * w + cx;
    float pcy = dy * h + cy;
    float pw  = expf(dw) * w;
    float ph  = expf(dh) * h;

    float x1 = fminf(fmaxf(pcx - 0.5f * pw, 0.0f), IMG);
    float y1 = fminf(fmaxf(pcy - 0.5f * ph, 0.0f), IMG);
    float x2 = fminf(fmaxf(pcx + 0.5f * pw, 0.0f), IMG);
    float y2 = fminf(fmaxf(pcy + 0.5f * ph, 0.0f), IMG);

    g_bx1[i] = x1; g_by1[i] = y1; g_bx2[i] = x2; g_by2[i] = y2;
    g_bar[i] = (x2 - x1) * (y2 - y1);
    g_bsc[i] = sc;
}

// ---------------- NMS bitmask ----------------
__global__ void nms_mask_kernel()
{
    const int bi = blockIdx.y, bj = blockIdx.x;
    const int t  = threadIdx.x;
    if (bj < bi) return;

    __shared__ float sx1[64], sy1[64], sx2[64], sy2[64], sa[64];
    int j0 = bj * 64;
    int j  = j0 + t;
    if (j < TOPK) {
        sx1[t] = g_bx1[j]; sy1[t] = g_by1[j];
        sx2[t] = g_bx2[j]; sy2[t] = g_by2[j];
        sa[t]  = g_bar[j];
    }
    __syncthreads();

    int i = bi * 64 + t;
    if (i >= TOPK) return;
    float bx1 = g_bx1[i], by1 = g_by1[i], bx2 = g_bx2[i], by2 = g_by2[i], ba = g_bar[i];

    unsigned long long bits = 0;
    int jmax = min(64, TOPK - j0);
    for (int jj = 0; jj < jmax; jj++) {
        int jg = j0 + jj;
        if (jg <= i) continue;
        float ix = fminf(bx2, sx2[jj]) - fmaxf(bx1, sx1[jj]);
        float iy = fminf(by2, sy2[jj]) - fmaxf(by1, sy1[jj]);
        ix = fmaxf(ix, 0.0f);
        iy = fmaxf(iy, 0.0f);
        float inter = ix * iy;
        float iou = inter / (ba + sa[jj] - inter);
        if (iou > NMSTHR) bits |= (1ULL << jj);
    }
    g_mask[(size_t)i * NMSW + bj] = bits;
}

// ---------------- greedy scan: smem diag prefetch + MLP OR-gather ----------
__global__ void nms_scan_kernel()
{
    __shared__ unsigned long long s_diag[64];
    __shared__ unsigned long long s_alive;
    __shared__ int s_cnt;
    const int t = threadIdx.x;            // 192 threads
    if (t == 0) s_cnt = 0;
    for (int j = t; j < POSTK; j += blockDim.x) g_keep[j] = 0;

    unsigned long long remv = 0;          // removal word owned by thread t

    for (int b = 0; b < NMSW; b++) {
        __syncthreads();
        int n = min(64, TOPK - b * 64);
        // prefetch diagonal words (parallel L2 loads) into smem
        if (t < n) s_diag[t] = g_mask[(size_t)(b * 64 + t) * NMSW + b];
        __syncthreads();

        if (t == b) {
            unsigned long long w = remv;
            unsigned long long alive = 0;
            int cnt = s_cnt;
            for (int bit = 0; bit < n; bit++) {
                if (!((w >> bit) & 1ULL)) {
                    alive |= (1ULL << bit);
                    if (cnt < POSTK) g_keep[cnt++] = b * 64 + bit;
                    w |= s_diag[bit];
                }
            }
            s_cnt = cnt;
            s_alive = alive;
            remv = w;
        }
        __syncthreads();

        if (s_cnt >= POSTK) break;  // first 2000 kept fixed; rest irrelevant

        if (t < NMSW && t > b) {
            unsigned long long am = s_alive;
            while (am) {
                int b0, b1 = -1, b2 = -1, b3 = -1;
                b0 = __ffsll((long long)am) - 1; am &= am - 1;
                if (am) { b1 = __ffsll((long long)am) - 1; am &= am - 1; }
                if (am) { b2 = __ffsll((long long)am) - 1; am &= am - 1; }
                if (am) { b3 = __ffsll((long long)am) - 1; am &= am - 1; }
                unsigned long long v0 = g_mask[(size_t)(b * 64 + b0) * NMSW + t];
                unsigned long long v1 = (b1 >= 0) ? g_mask[(size_t)(b * 64 + b1) * NMSW + t] : 0ULL;
                unsigned long long v2 = (b2 >= 0) ? g_mask[(size_t)(b * 64 + b2) * NMSW + t] : 0ULL;
                unsigned long long v3 = (b3 >= 0) ? g_mask[(size_t)(b * 64 + b3) * NMSW + t] : 0ULL;
                remv |= (v0 | v1) | (v2 | v3);
            }
        }
    }
}

// ---------------- gather output [2000,5] ----------------
__global__ void output_kernel(float* __restrict__ out)
{
    int j = blockIdx.x * 256 + threadIdx.x;
    if (j >= POSTK) return;
    int k = g_keep[j];
    out[j * 5 + 0] = g_bx1[k];
    out[j * 5 + 1] = g_by1[k];
    out[j * 5 + 2] = g_bx2[k];
    out[j * 5 + 3] = g_by2[k];
    out[j * 5 + 4] = g_bsc[k];
}

// ---------------- host launch ----------------
extern "C" void kernel_launch(void* const* d_in, const int* in_sizes, int n_in,
                              void* d_out, int out_size)
{
    (void)in_sizes; (void)n_in; (void)out_size;
    const float* feat  = (const float*)d_in[1];
    const float* Wconv = (const float*)d_in[2];
    const float* bconv = (const float*)d_in[3];
    const float* Wcls  = (const float*)d_in[4];
    const float* bcls  = (const float*)d_in[5];
    const float* Wbb   = (const float*)d_in[6];
    const float* bbb   = (const float*)d_in[7];
    float* out = (float*)d_out;

    void *p_sc, *p_idx, *p_scs, *p_idxs, *p_tmp;
    cudaGetSymbolAddress(&p_sc,   g_scores);
    cudaGetSymbolAddress(&p_idx,  g_sidx);
    cudaGetSymbolAddress(&p_scs,  g_scores_s);
    cudaGetSymbolAddress(&p_idxs, g_sidx_s);
    cudaGetSymbolAddress(&p_tmp,  g_cubtmp);

    static bool attr_done = false;
    if (!attr_done) {
        cudaFuncSetAttribute(conv1_kernel,
                             cudaFuncAttributeMaxDynamicSharedMemorySize,
                             CONV1_SMEM);
        attr_done = true;
    }

    conv1_kernel<<<dim3(79, 8), 256, CONV1_SMEM>>>(feat, Wconv, bconv);
    conv2_kernel<<<157, 160>>>(Wcls, bcls, Wbb, bbb);

    size_t tmp_bytes = sizeof(g_cubtmp);
    cub::DeviceRadixSort::SortPairsDescending(
        p_tmp, tmp_bytes,
        (const float*)p_sc, (float*)p_scs,
        (const int*)p_idx,  (int*)p_idxs,
        NS, 0, 32, (cudaStream_t)0);

    decode_kernel<<<40, 256>>>();
    nms_mask_kernel<<<dim3(NMSW, NMSW), 64>>>();
    nms_scan_kernel<<<1, 192>>>();
    output_kernel<<<8, 256>>>(out);
}